// round 14
// baseline (speedup 1.0000x reference)
#include <cuda_runtime.h>

#define GA 444           // A blocks (3 per SM)
#define GB 592           // B blocks (4 per SM)
#define MAXB 65536

__device__ float g_sg[MAXB * 72];   // per-elem: s2[64] then gss[8]

__device__ __forceinline__ float sigm(float v) { return 1.0f / (1.0f + __expf(-v)); }

__device__ __forceinline__ unsigned long long ffma2(unsigned long long a,
                                                    unsigned long long b,
                                                    unsigned long long c) {
    unsigned long long d;
    asm("fma.rn.f32x2 %0, %1, %2, %3;" : "=l"(d) : "l"(a), "l"(b), "l"(c));
    return d;
}
union f4u { float4 f; unsigned long long u[2]; };

// fold-reduce 8 lane-local values over 32 lanes; returns out[(lane>>2)&7] in each 4-lane group
__device__ __forceinline__ float fold_reduce8(const float* v, int lane) {
    const unsigned FULL = 0xffffffffu;
    bool h16 = (lane & 16) != 0;
    float w[4];
    #pragma unroll
    for (int i = 0; i < 4; ++i) {
        float send = h16 ? v[i] : v[i + 4];
        float t = __shfl_xor_sync(FULL, send, 16);
        w[i] = (h16 ? v[i + 4] : v[i]) + t;
    }
    bool h8 = (lane & 8) != 0;
    float u[2];
    #pragma unroll
    for (int i = 0; i < 2; ++i) {
        float send = h8 ? w[i] : w[i + 2];
        float t = __shfl_xor_sync(FULL, send, 8);
        u[i] = (h8 ? w[i + 2] : w[i]) + t;
    }
    bool h4 = (lane & 4) != 0;
    {
        float send = h4 ? u[0] : u[1];
        float t = __shfl_xor_sync(FULL, send, 4);
        u[0] = (h4 ? u[1] : u[0]) + t;
    }
    u[0] += __shfl_xor_sync(FULL, u[0], 2);
    u[0] += __shfl_xor_sync(FULL, u[0], 1);
    return u[0];
}

// =================== Kernel A: MLP -> s2, gss (round-8 proven) ================================
struct SmemA {                      // ~47 KB
    float WbT[32][64];
    float WshT[64][64];
    float haltT[64][32];
    float s2s[8][4][64];
    float s1s[8][4][32];
    float WbitT[8][32];
    float Weng[64], Wimp[64];
    float Wsur[32], Wgate[32];
    float bbit[32], bsh[64];
    float haltb[4];
    float beng, bimp, bsur, bgate;
};

__global__ void __launch_bounds__(256, 3)
org_mlp(const float* __restrict__ x,
        const float* __restrict__ W_bit, const float* __restrict__ b_bit,
        const float* __restrict__ W_bridge, const float* __restrict__ W_sh,
        const float* __restrict__ b_sh, const float* __restrict__ W_eng,
        const float* __restrict__ b_eng, const float* __restrict__ W_imp,
        const float* __restrict__ b_imp, const float* __restrict__ W_sur,
        const float* __restrict__ b_sur, const float* __restrict__ W_gate,
        const float* __restrict__ b_gate, const float* __restrict__ halt_w,
        const float* __restrict__ halt_b, int B)
{
    extern __shared__ float smraw[];
    SmemA* S = reinterpret_cast<SmemA*>(smraw);
    const int tid = threadIdx.x;
    const int warp = tid >> 5, lane = tid & 31;
    const unsigned FULL = 0xffffffffu;

    for (int i = tid; i < 2048; i += 256) { int k = i >> 6, m = i & 63; (&S->WbT[0][0])[i]   = W_bridge[m * 32 + k]; }
    for (int i = tid; i < 4096; i += 256) { int m = i >> 6, o = i & 63; (&S->WshT[0][0])[i]  = W_sh[o * 64 + m]; }
    for (int i = tid; i < 2048; i += 256) { int m = i >> 5, s = i & 31; (&S->haltT[0][0])[i] = halt_w[s * 64 + m]; }
    (&S->WbitT[0][0])[tid] = W_bit[(tid & 31) * 8 + (tid >> 5)];
    if (tid < 64) { S->Weng[tid] = W_eng[tid]; S->Wimp[tid] = W_imp[tid]; S->bsh[tid] = b_sh[tid]; }
    if (tid < 32) { S->Wsur[tid] = W_sur[tid]; S->Wgate[tid] = W_gate[tid]; S->bbit[tid] = b_bit[tid]; }
    if (tid < 4)  S->haltb[tid] = halt_b[tid];
    if (tid == 0) { S->beng = b_eng[0]; S->bimp = b_imp[0]; S->bsur = b_sur[0]; S->bgate = b_gate[0]; }
    __syncthreads();

    float* s1w = &S->s1s[warp][0][0];
    float* s2w = &S->s2s[warp][0][0];

    for (int e0 = blockIdx.x * 32 + warp * 4; e0 < B; e0 += GA * 32) {
        // ---- s1 ----
        float xv = x[(size_t)e0 * 8 + lane];
        float s1v[4];
        #pragma unroll
        for (int e = 0; e < 4; ++e) {
            float a = S->bbit[lane];
            #pragma unroll
            for (int j = 0; j < 8; ++j) {
                float xj = __shfl_sync(FULL, xv, e * 8 + j);
                a = fmaf(xj, S->WbitT[j][lane], a);
            }
            s1v[e] = a;
            s1w[e * 32 + lane] = a;
        }
        // ---- surprise ----
        float sur[4];
        #pragma unroll
        for (int e = 0; e < 4; ++e) {
            float a = s1v[e] * S->Wsur[lane];
            float b = s1v[e] * S->Wgate[lane];
            #pragma unroll
            for (int s = 16; s; s >>= 1) {
                a += __shfl_xor_sync(FULL, a, s);
                b += __shfl_xor_sync(FULL, b, s);
            }
            sur[e] = sigm(a + S->bsur) * sigm(b + S->bgate);
        }
        __syncwarp();

        // ---- s2 = tanh(s1 @ Wb^T); store to smem AND global ----
        {
            float acc0[4] = {0,0,0,0}, acc1[4] = {0,0,0,0};
            #pragma unroll
            for (int k4 = 0; k4 < 8; ++k4) {
                float4 s14[4];
                #pragma unroll
                for (int e = 0; e < 4; ++e) s14[e] = *(const float4*)&s1w[e * 32 + k4 * 4];
                #pragma unroll
                for (int kk = 0; kk < 4; ++kk) {
                    float2 w2 = *(const float2*)&S->WbT[k4 * 4 + kk][2 * lane];
                    #pragma unroll
                    for (int e = 0; e < 4; ++e) {
                        float sv = (&s14[e].x)[kk];
                        acc0[e] = fmaf(sv, w2.x, acc0[e]);
                        acc1[e] = fmaf(sv, w2.y, acc1[e]);
                    }
                }
            }
            #pragma unroll
            for (int e = 0; e < 4; ++e) {
                float2 t2; t2.x = tanhf(acc0[e]); t2.y = tanhf(acc1[e]);
                *(float2*)&s2w[e * 64 + 2 * lane] = t2;
                *(float2*)&g_sg[(size_t)(e0 + e) * 72 + 2 * lane] = t2;
            }
        }
        __syncwarp();

        // ---- merged hg + halt loop ----
        float engimp[4];
        float ha[4] = {0,0,0,0};
        {
            float h0[4] = {0,0,0,0}, h1[4] = {0,0,0,0};
            #pragma unroll
            for (int m4 = 0; m4 < 16; ++m4) {
                float4 s24[4];
                #pragma unroll
                for (int e = 0; e < 4; ++e) s24[e] = *(const float4*)&s2w[e * 64 + m4 * 4];
                #pragma unroll
                for (int mm = 0; mm < 4; ++mm) {
                    float2 w2 = *(const float2*)&S->WshT[m4 * 4 + mm][2 * lane];
                    float hw  = S->haltT[m4 * 4 + mm][lane];
                    #pragma unroll
                    for (int e = 0; e < 4; ++e) {
                        float sv = (&s24[e].x)[mm];
                        h0[e] = fmaf(sv, w2.x, h0[e]);
                        h1[e] = fmaf(sv, w2.y, h1[e]);
                        ha[e] = fmaf(sv, hw,   ha[e]);
                    }
                }
            }
            float we0 = S->Weng[2 * lane], we1 = S->Weng[2 * lane + 1];
            float wi0 = S->Wimp[2 * lane], wi1 = S->Wimp[2 * lane + 1];
            float bs0 = S->bsh[2 * lane],  bs1 = S->bsh[2 * lane + 1];
            #pragma unroll
            for (int e = 0; e < 4; ++e) {
                float g0 = fmaxf(h0[e] + bs0, 0.f);
                float g1 = fmaxf(h1[e] + bs1, 0.f);
                float pe = g0 * we0 + g1 * we1;
                float pi = g0 * wi0 + g1 * wi1;
                #pragma unroll
                for (int s = 16; s; s >>= 1) {
                    pe += __shfl_xor_sync(FULL, pe, s);
                    pi += __shfl_xor_sync(FULL, pi, s);
                }
                engimp[e] = sigm(pe + S->beng) * sigm(pi + S->bimp);
            }
        }

        // ---- halt sigmoid -> gss -> global ----
        float hb = S->haltb[lane >> 3];
        #pragma unroll
        for (int e = 0; e < 4; ++e) {
            float hv = sigm(ha[e] + hb);
            hv += __shfl_xor_sync(FULL, hv, 8);
            hv += __shfl_xor_sync(FULL, hv, 16);
            float g = engimp[e] * sur[e] * hv;
            if (lane < 8) g_sg[(size_t)(e0 + e) * 72 + 64 + lane] = g;
        }
        __syncwarp();
    }
}

// =================== Kernel B: H stream + gate fold + fold-reduce readout =====================
struct SmemB {                      // ~24.6 KB
    float dg[2048];
    float Wr[8][512];
    float bread[8];
};

__global__ void __launch_bounds__(256, 4)
org_stream(const float* __restrict__ H, const float* __restrict__ W_read,
           const float* __restrict__ b_read, const float* __restrict__ decays,
           float* __restrict__ out, int B)
{
    extern __shared__ float smraw[];
    SmemB* Sb = reinterpret_cast<SmemB*>(smraw);
    const int tid = threadIdx.x;
    const int warp = tid >> 5, lane = tid & 31;

    for (int i = tid; i < 2048; i += 256) Sb->dg[i] = sigm(decays[i]);
    for (int i = tid; i < 4096; i += 256) (&Sb->Wr[0][0])[i] = 0.25f * W_read[i];
    if (tid < 8) Sb->bread[tid] = b_read[tid];
    __syncthreads();

    const int og = (lane >> 2) & 7;          // output owned by this lane's 4-group
    const float brd = Sb->bread[og];

    for (int b0 = ((int)blockIdx.x * 8 + warp) * 2; b0 < B; b0 += GB * 16) {
        const float4* H0 = (const float4*)H + (size_t)b0 * 512;
        f4u rs[2][4];
        #pragma unroll
        for (int e = 0; e < 2; ++e)
            #pragma unroll
            for (int c = 0; c < 4; ++c) rs[e][c].f = make_float4(0.f, 0.f, 0.f, 0.f);

        #pragma unroll
        for (int l = 0; l < 4; ++l) {
            f4u t[2][4];
            #pragma unroll
            for (int e = 0; e < 2; ++e)
                #pragma unroll
                for (int c = 0; c < 4; ++c)
                    t[e][c].f = __ldcs(H0 + (size_t)e * 512 + l * 128 + c * 32 + lane);
            #pragma unroll
            for (int c = 0; c < 4; ++c) {
                f4u d; d.f = *(const float4*)&Sb->dg[l * 512 + c * 128 + 4 * lane];
                #pragma unroll
                for (int e = 0; e < 2; ++e) {
                    rs[e][c].u[0] = ffma2(t[e][c].u[0], d.u[0], rs[e][c].u[0]);
                    rs[e][c].u[1] = ffma2(t[e][c].u[1], d.u[1], rs[e][c].u[1]);
                }
            }
        }

        // ---- fold gate term: rs[e][c] += gss[r(c)] * s2[m] ----
        #pragma unroll
        for (int e = 0; e < 2; ++e) {
            const float* sg = &g_sg[(size_t)(b0 + e) * 72];
            float4 s2m = *(const float4*)&sg[(4 * lane) & 63];
            #pragma unroll
            for (int c = 0; c < 4; ++c) {
                float g = sg[64 + (lane >> 4) + 2 * c];
                rs[e][c].f.x = fmaf(g, s2m.x, rs[e][c].f.x);
                rs[e][c].f.y = fmaf(g, s2m.y, rs[e][c].f.y);
                rs[e][c].f.z = fmaf(g, s2m.z, rs[e][c].f.z);
                rs[e][c].f.w = fmaf(g, s2m.w, rs[e][c].f.w);
            }
        }

        // ---- per-lane partials for all 8 outputs, both elems ----
        float v0[8], v1[8];
        #pragma unroll
        for (int o = 0; o < 8; ++o) {
            unsigned long long a0 = 0ull, a1 = 0ull, c0 = 0ull, c1 = 0ull;
            #pragma unroll
            for (int c = 0; c < 4; ++c) {
                f4u w; w.f = *(const float4*)&Sb->Wr[o][c * 128 + 4 * lane];
                a0 = ffma2(rs[0][c].u[0], w.u[0], a0);
                a1 = ffma2(rs[0][c].u[1], w.u[1], a1);
                c0 = ffma2(rs[1][c].u[0], w.u[0], c0);
                c1 = ffma2(rs[1][c].u[1], w.u[1], c1);
            }
            f4u pa; pa.u[0] = a0; pa.u[1] = a1;
            f4u pc; pc.u[0] = c0; pc.u[1] = c1;
            v0[o] = (pa.f.x + pa.f.y) + (pa.f.z + pa.f.w);
            v1[o] = (pc.f.x + pc.f.y) + (pc.f.z + pc.f.w);
        }

        // ---- fold-reduce: 9 shfl per elem, coalesced 8-lane store ----
        float z0 = fold_reduce8(v0, lane);
        float z1 = fold_reduce8(v1, lane);
        if ((lane & 3) == 0) {
            out[(size_t)b0 * 8 + og]       = z0 + brd;
            out[(size_t)(b0 + 1) * 8 + og] = z1 + brd;
        }
    }
}

extern "C" void kernel_launch(void* const* d_in, const int* in_sizes, int n_in,
                              void* d_out, int out_size) {
    const float* x        = (const float*)d_in[0];
    const float* H        = (const float*)d_in[1];
    const float* W_bit    = (const float*)d_in[2];
    const float* b_bit    = (const float*)d_in[3];
    const float* W_bridge = (const float*)d_in[4];
    const float* W_read   = (const float*)d_in[5];
    const float* b_read   = (const float*)d_in[6];
    const float* W_sh     = (const float*)d_in[7];
    const float* b_sh     = (const float*)d_in[8];
    const float* W_eng    = (const float*)d_in[9];
    const float* b_eng    = (const float*)d_in[10];
    const float* W_imp    = (const float*)d_in[11];
    const float* b_imp    = (const float*)d_in[12];
    const float* W_sur    = (const float*)d_in[13];
    const float* b_sur    = (const float*)d_in[14];
    const float* W_gate   = (const float*)d_in[15];
    const float* b_gate   = (const float*)d_in[16];
    const float* decays   = (const float*)d_in[17];
    const float* halt_w   = (const float*)d_in[18];
    const float* halt_b   = (const float*)d_in[19];
    const int B = in_sizes[0] / 8;
    float* out = (float*)d_out;

    cudaFuncSetAttribute(org_mlp, cudaFuncAttributeMaxDynamicSharedMemorySize,
                         (int)sizeof(SmemA));
    cudaFuncSetAttribute(org_stream, cudaFuncAttributeMaxDynamicSharedMemorySize,
                         (int)sizeof(SmemB));

    org_mlp<<<GA, 256, sizeof(SmemA)>>>(x, W_bit, b_bit, W_bridge, W_sh, b_sh,
                                        W_eng, b_eng, W_imp, b_imp, W_sur, b_sur,
                                        W_gate, b_gate, halt_w, halt_b, B);

    org_stream<<<GB, 256, sizeof(SmemB)>>>(H, W_read, b_read, decays, out, B);
}

// round 15
// speedup vs baseline: 1.0505x; 1.0505x over previous
#include <cuda_runtime.h>

#define GA 444           // A blocks (3 per SM)
#define GBB 148          // B blocks (1 per SM)
#define NWB (GBB * 8)    // 1184 streaming warps
#define MAXB 65536

__device__ float g_sg[MAXB * 72];   // per-elem: s2[64] then gss[8]

__device__ __forceinline__ float sigm(float v) { return 1.0f / (1.0f + __expf(-v)); }

__device__ __forceinline__ unsigned long long ffma2(unsigned long long a,
                                                    unsigned long long b,
                                                    unsigned long long c) {
    unsigned long long d;
    asm("fma.rn.f32x2 %0, %1, %2, %3;" : "=l"(d) : "l"(a), "l"(b), "l"(c));
    return d;
}
union f4u { float4 f; float a[4]; unsigned long long u[2]; };

__device__ __forceinline__ void cp16(unsigned s, const void* g) {
    asm volatile("cp.async.cg.shared.global [%0], [%1], 16;" :: "r"(s), "l"(g));
}
#define CP_COMMIT() asm volatile("cp.async.commit_group;" ::: "memory")
#define CP_WAIT2()  asm volatile("cp.async.wait_group 2;" ::: "memory")
#define CP_WAIT0()  asm volatile("cp.async.wait_group 0;" ::: "memory")

// fold-reduce 8 lane-local values; result for o=(lane>>2)&7 in each 4-lane group
__device__ __forceinline__ float fold_reduce8(const float* v, int lane) {
    const unsigned FULL = 0xffffffffu;
    bool h16 = (lane & 16) != 0;
    float w[4];
    #pragma unroll
    for (int i = 0; i < 4; ++i) {
        float send = h16 ? v[i] : v[i + 4];
        float t = __shfl_xor_sync(FULL, send, 16);
        w[i] = (h16 ? v[i + 4] : v[i]) + t;
    }
    bool h8 = (lane & 8) != 0;
    float u[2];
    #pragma unroll
    for (int i = 0; i < 2; ++i) {
        float send = h8 ? w[i] : w[i + 2];
        float t = __shfl_xor_sync(FULL, send, 8);
        u[i] = (h8 ? w[i + 2] : w[i]) + t;
    }
    bool h4 = (lane & 4) != 0;
    {
        float send = h4 ? u[0] : u[1];
        float t = __shfl_xor_sync(FULL, send, 4);
        u[0] = (h4 ? u[1] : u[0]) + t;
    }
    u[0] += __shfl_xor_sync(FULL, u[0], 2);
    u[0] += __shfl_xor_sync(FULL, u[0], 1);
    return u[0];
}

// =================== Kernel A: MLP -> s2, gss (round-8 proven) ================================
struct SmemA {                      // ~47 KB
    float WbT[32][64];
    float WshT[64][64];
    float haltT[64][32];
    float s2s[8][4][64];
    float s1s[8][4][32];
    float WbitT[8][32];
    float Weng[64], Wimp[64];
    float Wsur[32], Wgate[32];
    float bbit[32], bsh[64];
    float haltb[4];
    float beng, bimp, bsur, bgate;
};

__global__ void __launch_bounds__(256, 3)
org_mlp(const float* __restrict__ x,
        const float* __restrict__ W_bit, const float* __restrict__ b_bit,
        const float* __restrict__ W_bridge, const float* __restrict__ W_sh,
        const float* __restrict__ b_sh, const float* __restrict__ W_eng,
        const float* __restrict__ b_eng, const float* __restrict__ W_imp,
        const float* __restrict__ b_imp, const float* __restrict__ W_sur,
        const float* __restrict__ b_sur, const float* __restrict__ W_gate,
        const float* __restrict__ b_gate, const float* __restrict__ halt_w,
        const float* __restrict__ halt_b, int B)
{
    extern __shared__ float smraw[];
    SmemA* S = reinterpret_cast<SmemA*>(smraw);
    const int tid = threadIdx.x;
    const int warp = tid >> 5, lane = tid & 31;
    const unsigned FULL = 0xffffffffu;

    for (int i = tid; i < 2048; i += 256) { int k = i >> 6, m = i & 63; (&S->WbT[0][0])[i]   = W_bridge[m * 32 + k]; }
    for (int i = tid; i < 4096; i += 256) { int m = i >> 6, o = i & 63; (&S->WshT[0][0])[i]  = W_sh[o * 64 + m]; }
    for (int i = tid; i < 2048; i += 256) { int m = i >> 5, s = i & 31; (&S->haltT[0][0])[i] = halt_w[s * 64 + m]; }
    (&S->WbitT[0][0])[tid] = W_bit[(tid & 31) * 8 + (tid >> 5)];
    if (tid < 64) { S->Weng[tid] = W_eng[tid]; S->Wimp[tid] = W_imp[tid]; S->bsh[tid] = b_sh[tid]; }
    if (tid < 32) { S->Wsur[tid] = W_sur[tid]; S->Wgate[tid] = W_gate[tid]; S->bbit[tid] = b_bit[tid]; }
    if (tid < 4)  S->haltb[tid] = halt_b[tid];
    if (tid == 0) { S->beng = b_eng[0]; S->bimp = b_imp[0]; S->bsur = b_sur[0]; S->bgate = b_gate[0]; }
    __syncthreads();

    float* s1w = &S->s1s[warp][0][0];
    float* s2w = &S->s2s[warp][0][0];

    for (int e0 = blockIdx.x * 32 + warp * 4; e0 < B; e0 += GA * 32) {
        float xv = x[(size_t)e0 * 8 + lane];
        float s1v[4];
        #pragma unroll
        for (int e = 0; e < 4; ++e) {
            float a = S->bbit[lane];
            #pragma unroll
            for (int j = 0; j < 8; ++j) {
                float xj = __shfl_sync(FULL, xv, e * 8 + j);
                a = fmaf(xj, S->WbitT[j][lane], a);
            }
            s1v[e] = a;
            s1w[e * 32 + lane] = a;
        }
        float sur[4];
        #pragma unroll
        for (int e = 0; e < 4; ++e) {
            float a = s1v[e] * S->Wsur[lane];
            float b = s1v[e] * S->Wgate[lane];
            #pragma unroll
            for (int s = 16; s; s >>= 1) {
                a += __shfl_xor_sync(FULL, a, s);
                b += __shfl_xor_sync(FULL, b, s);
            }
            sur[e] = sigm(a + S->bsur) * sigm(b + S->bgate);
        }
        __syncwarp();

        {
            float acc0[4] = {0,0,0,0}, acc1[4] = {0,0,0,0};
            #pragma unroll
            for (int k4 = 0; k4 < 8; ++k4) {
                float4 s14[4];
                #pragma unroll
                for (int e = 0; e < 4; ++e) s14[e] = *(const float4*)&s1w[e * 32 + k4 * 4];
                #pragma unroll
                for (int kk = 0; kk < 4; ++kk) {
                    float2 w2 = *(const float2*)&S->WbT[k4 * 4 + kk][2 * lane];
                    #pragma unroll
                    for (int e = 0; e < 4; ++e) {
                        float sv = (&s14[e].x)[kk];
                        acc0[e] = fmaf(sv, w2.x, acc0[e]);
                        acc1[e] = fmaf(sv, w2.y, acc1[e]);
                    }
                }
            }
            #pragma unroll
            for (int e = 0; e < 4; ++e) {
                float2 t2; t2.x = tanhf(acc0[e]); t2.y = tanhf(acc1[e]);
                *(float2*)&s2w[e * 64 + 2 * lane] = t2;
                *(float2*)&g_sg[(size_t)(e0 + e) * 72 + 2 * lane] = t2;
            }
        }
        __syncwarp();

        float engimp[4];
        float ha[4] = {0,0,0,0};
        {
            float h0[4] = {0,0,0,0}, h1[4] = {0,0,0,0};
            #pragma unroll
            for (int m4 = 0; m4 < 16; ++m4) {
                float4 s24[4];
                #pragma unroll
                for (int e = 0; e < 4; ++e) s24[e] = *(const float4*)&s2w[e * 64 + m4 * 4];
                #pragma unroll
                for (int mm = 0; mm < 4; ++mm) {
                    float2 w2 = *(const float2*)&S->WshT[m4 * 4 + mm][2 * lane];
                    float hw  = S->haltT[m4 * 4 + mm][lane];
                    #pragma unroll
                    for (int e = 0; e < 4; ++e) {
                        float sv = (&s24[e].x)[mm];
                        h0[e] = fmaf(sv, w2.x, h0[e]);
                        h1[e] = fmaf(sv, w2.y, h1[e]);
                        ha[e] = fmaf(sv, hw,   ha[e]);
                    }
                }
            }
            float we0 = S->Weng[2 * lane], we1 = S->Weng[2 * lane + 1];
            float wi0 = S->Wimp[2 * lane], wi1 = S->Wimp[2 * lane + 1];
            float bs0 = S->bsh[2 * lane],  bs1 = S->bsh[2 * lane + 1];
            #pragma unroll
            for (int e = 0; e < 4; ++e) {
                float g0 = fmaxf(h0[e] + bs0, 0.f);
                float g1 = fmaxf(h1[e] + bs1, 0.f);
                float pe = g0 * we0 + g1 * we1;
                float pi = g0 * wi0 + g1 * wi1;
                #pragma unroll
                for (int s = 16; s; s >>= 1) {
                    pe += __shfl_xor_sync(FULL, pe, s);
                    pi += __shfl_xor_sync(FULL, pi, s);
                }
                engimp[e] = sigm(pe + S->beng) * sigm(pi + S->bimp);
            }
        }

        float hb = S->haltb[lane >> 3];
        #pragma unroll
        for (int e = 0; e < 4; ++e) {
            float hv = sigm(ha[e] + hb);
            hv += __shfl_xor_sync(FULL, hv, 8);
            hv += __shfl_xor_sync(FULL, hv, 16);
            float g = engimp[e] * sur[e] * hv;
            if (lane < 8) g_sg[(size_t)(e0 + e) * 72 + 64 + lane] = g;
        }
        __syncwarp();
    }
}

// =================== Kernel B: cp.async triple-buffered H stream ==============================
struct SmemB {                      // ~200 KB -> 1 CTA/SM
    float dg[2048];                 // 8 KB
    float buf[8][3][2048];          // 192 KB: [warp][ring slot][elem floats]
};

__global__ void __launch_bounds__(256, 1)
org_stream(const float* __restrict__ H, const float* __restrict__ W_read,
           const float* __restrict__ b_read, const float* __restrict__ decays,
           float* __restrict__ out, int B)
{
    extern __shared__ float smraw[];
    SmemB* Sb = reinterpret_cast<SmemB*>(smraw);
    const int tid = threadIdx.x;
    const int warp = tid >> 5, lane = tid & 31;

    for (int i = tid; i < 2048; i += 256) Sb->dg[i] = sigm(decays[i]);
    __syncthreads();

    // Wr resident in registers: 0.25*W_read[o][c*128 + 4*lane .. +3]
    f4u Wreg[8][4];
    #pragma unroll
    for (int o = 0; o < 8; ++o)
        #pragma unroll
        for (int c = 0; c < 4; ++c) {
            f4u w; w.f = *(const float4*)&W_read[o * 512 + c * 128 + lane * 4];
            w.f.x *= 0.25f; w.f.y *= 0.25f; w.f.z *= 0.25f; w.f.w *= 0.25f;
            Wreg[o][c] = w;
        }

    const int og = (lane >> 2) & 7;
    const float brd = b_read[og];

    float* bufw = &Sb->buf[warp][0][0];
    unsigned bufu = (unsigned)__cvta_generic_to_shared(bufw) + lane * 16u;

    const int e0 = (int)blockIdx.x * 8 + warp;

    // prologue: prefetch e0 -> slot0, e0+NWB -> slot1 (clamped)
    {
        const float* src = H + (size_t)e0 * 2048 + lane * 4;
        #pragma unroll
        for (int i = 0; i < 16; ++i) cp16(bufu + i * 512u, src + i * 128);
        CP_COMMIT();
        int e1 = e0 + NWB; if (e1 >= B) e1 = 0;
        const float* src1 = H + (size_t)e1 * 2048 + lane * 4;
        #pragma unroll
        for (int i = 0; i < 16; ++i) cp16(bufu + 8192u + i * 512u, src1 + i * 128);
        CP_COMMIT();
    }

    int ph = 0;
    for (int e = e0; e < B; e += NWB) {
        // prefetch 2 ahead into slot (ph+2)%3 ; always one commit per iter
        {
            int ep = e + 2 * NWB; if (ep >= B) ep = 0;
            int php = ph + 2; if (php >= 3) php -= 3;
            const float* src = H + (size_t)ep * 2048 + lane * 4;
            unsigned dst = bufu + (unsigned)php * 8192u;
            #pragma unroll
            for (int i = 0; i < 16; ++i) cp16(dst + i * 512u, src + i * 128);
            CP_COMMIT();
        }
        CP_WAIT2();                               // current slot's group has landed

        // ---- decay-reduce from smem ring ----
        const float* bw = bufw + ph * 2048;
        f4u rs[4];
        #pragma unroll
        for (int c = 0; c < 4; ++c) rs[c].f = make_float4(0.f, 0.f, 0.f, 0.f);
        #pragma unroll
        for (int l = 0; l < 4; ++l) {
            #pragma unroll
            for (int c = 0; c < 4; ++c) {
                f4u t; t.f = *(const float4*)&bw[l * 512 + c * 128 + lane * 4];
                f4u d; d.f = *(const float4*)&Sb->dg[l * 512 + c * 128 + lane * 4];
                rs[c].u[0] = ffma2(t.u[0], d.u[0], rs[c].u[0]);
                rs[c].u[1] = ffma2(t.u[1], d.u[1], rs[c].u[1]);
            }
        }

        // ---- gate fold ----
        {
            const float* sg = &g_sg[(size_t)e * 72];
            float4 s2m = *(const float4*)&sg[(4 * lane) & 63];
            #pragma unroll
            for (int c = 0; c < 4; ++c) {
                float g = sg[64 + (lane >> 4) + 2 * c];
                rs[c].f.x = fmaf(g, s2m.x, rs[c].f.x);
                rs[c].f.y = fmaf(g, s2m.y, rs[c].f.y);
                rs[c].f.z = fmaf(g, s2m.z, rs[c].f.z);
                rs[c].f.w = fmaf(g, s2m.w, rs[c].f.w);
            }
        }

        // ---- readout with register-resident Wr ----
        float v[8];
        #pragma unroll
        for (int o = 0; o < 8; ++o) {
            unsigned long long a0 = 0ull, a1 = 0ull;
            #pragma unroll
            for (int c = 0; c < 4; ++c) {
                a0 = ffma2(rs[c].u[0], Wreg[o][c].u[0], a0);
                a1 = ffma2(rs[c].u[1], Wreg[o][c].u[1], a1);
            }
            f4u pa; pa.u[0] = a0; pa.u[1] = a1;
            v[o] = (pa.f.x + pa.f.y) + (pa.f.z + pa.f.w);
        }
        float z = fold_reduce8(v, lane);
        if ((lane & 3) == 0) out[(size_t)e * 8 + og] = z + brd;

        ph = ph + 1; if (ph == 3) ph = 0;
    }
    CP_WAIT0();
}

extern "C" void kernel_launch(void* const* d_in, const int* in_sizes, int n_in,
                              void* d_out, int out_size) {
    const float* x        = (const float*)d_in[0];
    const float* H        = (const float*)d_in[1];
    const float* W_bit    = (const float*)d_in[2];
    const float* b_bit    = (const float*)d_in[3];
    const float* W_bridge = (const float*)d_in[4];
    const float* W_read   = (const float*)d_in[5];
    const float* b_read   = (const float*)d_in[6];
    const float* W_sh     = (const float*)d_in[7];
    const float* b_sh     = (const float*)d_in[8];
    const float* W_eng    = (const float*)d_in[9];
    const float* b_eng    = (const float*)d_in[10];
    const float* W_imp    = (const float*)d_in[11];
    const float* b_imp    = (const float*)d_in[12];
    const float* W_sur    = (const float*)d_in[13];
    const float* b_sur    = (const float*)d_in[14];
    const float* W_gate   = (const float*)d_in[15];
    const float* b_gate   = (const float*)d_in[16];
    const float* decays   = (const float*)d_in[17];
    const float* halt_w   = (const float*)d_in[18];
    const float* halt_b   = (const float*)d_in[19];
    const int B = in_sizes[0] / 8;
    float* out = (float*)d_out;

    cudaFuncSetAttribute(org_mlp, cudaFuncAttributeMaxDynamicSharedMemorySize,
                         (int)sizeof(SmemA));
    cudaFuncSetAttribute(org_stream, cudaFuncAttributeMaxDynamicSharedMemorySize,
                         (int)sizeof(SmemB));

    org_mlp<<<GA, 256, sizeof(SmemA)>>>(x, W_bit, b_bit, W_bridge, W_sh, b_sh,
                                        W_eng, b_eng, W_imp, b_imp, W_sur, b_sur,
                                        W_gate, b_gate, halt_w, halt_b, B);

    org_stream<<<GBB, 256, sizeof(SmemB)>>>(H, W_read, b_read, decays, out, B);
}

// round 16
// speedup vs baseline: 1.1106x; 1.0572x over previous
#include <cuda_runtime.h>

#define NBLK 148
#define STRIDE (NBLK * 8 * 4)    // 4736 elems per sweep

__device__ __forceinline__ float sigm(float v) { return 1.0f / (1.0f + __expf(-v)); }

__device__ __forceinline__ unsigned long long ffma2(unsigned long long a,
                                                    unsigned long long b,
                                                    unsigned long long c) {
    unsigned long long d;
    asm("fma.rn.f32x2 %0, %1, %2, %3;" : "=l"(d) : "l"(a), "l"(b), "l"(c));
    return d;
}
union f4u { float4 f; float a[4]; unsigned long long u[2]; };

__device__ __forceinline__ void cp16(unsigned s, const void* g) {
    asm volatile("cp.async.cg.shared.global [%0], [%1], 16;" :: "r"(s), "l"(g));
}
#define CP_COMMIT() asm volatile("cp.async.commit_group;" ::: "memory")
#define CP_WAIT1()  asm volatile("cp.async.wait_group 1;" ::: "memory")
#define CP_WAIT0()  asm volatile("cp.async.wait_group 0;" ::: "memory")

// fold-reduce 8 lane-local values; result for o=(lane>>2)&7 in each 4-lane group
__device__ __forceinline__ float fold_reduce8(const float* v, int lane) {
    const unsigned FULL = 0xffffffffu;
    bool h16 = (lane & 16) != 0;
    float w[4];
    #pragma unroll
    for (int i = 0; i < 4; ++i) {
        float send = h16 ? v[i] : v[i + 4];
        float t = __shfl_xor_sync(FULL, send, 16);
        w[i] = (h16 ? v[i + 4] : v[i]) + t;
    }
    bool h8 = (lane & 8) != 0;
    float u[2];
    #pragma unroll
    for (int i = 0; i < 2; ++i) {
        float send = h8 ? w[i] : w[i + 2];
        float t = __shfl_xor_sync(FULL, send, 8);
        u[i] = (h8 ? w[i + 2] : w[i]) + t;
    }
    bool h4 = (lane & 4) != 0;
    {
        float send = h4 ? u[0] : u[1];
        float t = __shfl_xor_sync(FULL, send, 4);
        u[0] = (h4 ? u[1] : u[0]) + t;
    }
    u[0] += __shfl_xor_sync(FULL, u[0], 2);
    u[0] += __shfl_xor_sync(FULL, u[0], 1);
    return u[0];
}

// ---------------- shared layout (~183 KB, 1 CTA/SM) -------------------------------------------
struct Smem {
    float dg[2048];          //  8 KB
    float buf[8][2][2048];   // 128 KB  [warp][slot][elem]
    float WbT[32][64];       //  8 KB
    float WshT[64][64];      // 16 KB
    float haltT[64][32];     //  8 KB
    float s2s[8][4][64];     //  8 KB
    float s1s[8][4][32];     //  4 KB
    float gss[8][4][8];      //  1 KB
    float WbitT[8][32];      //  1 KB
    float Weng[64], Wimp[64];
    float Wsur[32], Wgate[32];
    float bbit[32], bsh[64];
    float bread[8];
    float haltb[4];
    float beng, bimp, bsur, bgate;
};

// warp-cooperative MLP for 4 consecutive elements e0..e0+3 -> s2s/gss in smem
__device__ __forceinline__ void mlp4(Smem* S, const float* __restrict__ x, int e0,
                                     int lane, float* s1w, float* s2w, float* gssw) {
    const unsigned FULL = 0xffffffffu;
    // ---- s1 ----
    float xv = x[(size_t)e0 * 8 + lane];
    float s1v[4];
    #pragma unroll
    for (int e = 0; e < 4; ++e) {
        float a = S->bbit[lane];
        #pragma unroll
        for (int j = 0; j < 8; ++j) {
            float xj = __shfl_sync(FULL, xv, e * 8 + j);
            a = fmaf(xj, S->WbitT[j][lane], a);
        }
        s1v[e] = a;
        s1w[e * 32 + lane] = a;
    }
    // ---- surprise ----
    float sur[4];
    #pragma unroll
    for (int e = 0; e < 4; ++e) {
        float a = s1v[e] * S->Wsur[lane];
        float b = s1v[e] * S->Wgate[lane];
        #pragma unroll
        for (int s = 16; s; s >>= 1) {
            a += __shfl_xor_sync(FULL, a, s);
            b += __shfl_xor_sync(FULL, b, s);
        }
        sur[e] = sigm(a + S->bsur) * sigm(b + S->bgate);
    }
    __syncwarp();

    // ---- s2 = tanh(s1 @ Wb^T) ----
    {
        float acc0[4] = {0,0,0,0}, acc1[4] = {0,0,0,0};
        #pragma unroll
        for (int k4 = 0; k4 < 8; ++k4) {
            float4 s14[4];
            #pragma unroll
            for (int e = 0; e < 4; ++e) s14[e] = *(const float4*)&s1w[e * 32 + k4 * 4];
            #pragma unroll
            for (int kk = 0; kk < 4; ++kk) {
                float2 w2 = *(const float2*)&S->WbT[k4 * 4 + kk][2 * lane];
                #pragma unroll
                for (int e = 0; e < 4; ++e) {
                    float sv = (&s14[e].x)[kk];
                    acc0[e] = fmaf(sv, w2.x, acc0[e]);
                    acc1[e] = fmaf(sv, w2.y, acc1[e]);
                }
            }
        }
        #pragma unroll
        for (int e = 0; e < 4; ++e) {
            float2 t2; t2.x = tanhf(acc0[e]); t2.y = tanhf(acc1[e]);
            *(float2*)&s2w[e * 64 + 2 * lane] = t2;
        }
    }
    __syncwarp();

    // ---- merged hg + halt ----
    float engimp[4];
    float ha[4] = {0,0,0,0};
    {
        float h0[4] = {0,0,0,0}, h1[4] = {0,0,0,0};
        #pragma unroll
        for (int m4 = 0; m4 < 16; ++m4) {
            float4 s24[4];
            #pragma unroll
            for (int e = 0; e < 4; ++e) s24[e] = *(const float4*)&s2w[e * 64 + m4 * 4];
            #pragma unroll
            for (int mm = 0; mm < 4; ++mm) {
                float2 w2 = *(const float2*)&S->WshT[m4 * 4 + mm][2 * lane];
                float hw  = S->haltT[m4 * 4 + mm][lane];
                #pragma unroll
                for (int e = 0; e < 4; ++e) {
                    float sv = (&s24[e].x)[mm];
                    h0[e] = fmaf(sv, w2.x, h0[e]);
                    h1[e] = fmaf(sv, w2.y, h1[e]);
                    ha[e] = fmaf(sv, hw,   ha[e]);
                }
            }
        }
        float we0 = S->Weng[2 * lane], we1 = S->Weng[2 * lane + 1];
        float wi0 = S->Wimp[2 * lane], wi1 = S->Wimp[2 * lane + 1];
        float bs0 = S->bsh[2 * lane],  bs1 = S->bsh[2 * lane + 1];
        #pragma unroll
        for (int e = 0; e < 4; ++e) {
            float g0 = fmaxf(h0[e] + bs0, 0.f);
            float g1 = fmaxf(h1[e] + bs1, 0.f);
            float pe = g0 * we0 + g1 * we1;
            float pi = g0 * wi0 + g1 * wi1;
            #pragma unroll
            for (int s = 16; s; s >>= 1) {
                pe += __shfl_xor_sync(FULL, pe, s);
                pi += __shfl_xor_sync(FULL, pi, s);
            }
            engimp[e] = sigm(pe + S->beng) * sigm(pi + S->bimp);
        }
    }

    // ---- halt sigmoid -> gss (smem) ----
    float hb = S->haltb[lane >> 3];
    #pragma unroll
    for (int e = 0; e < 4; ++e) {
        float hv = sigm(ha[e] + hb);
        hv += __shfl_xor_sync(FULL, hv, 8);
        hv += __shfl_xor_sync(FULL, hv, 16);
        float g = engimp[e] * sur[e] * hv;
        if (lane < 8) gssw[e * 8 + lane] = g;
    }
    __syncwarp();
}

__device__ __forceinline__ void prefetch_elem(unsigned dst, const float* __restrict__ H,
                                              int e, int lane) {
    const float* src = H + (size_t)e * 2048 + lane * 4;
    #pragma unroll
    for (int i = 0; i < 16; ++i) cp16(dst + i * 512u, src + i * 128);
    CP_COMMIT();
}

__global__ void __launch_bounds__(256, 1)
org_all(const float* __restrict__ x, const float* __restrict__ H,
        const float* __restrict__ W_bit, const float* __restrict__ b_bit,
        const float* __restrict__ W_bridge, const float* __restrict__ W_read,
        const float* __restrict__ b_read, const float* __restrict__ W_sh,
        const float* __restrict__ b_sh, const float* __restrict__ W_eng,
        const float* __restrict__ b_eng, const float* __restrict__ W_imp,
        const float* __restrict__ b_imp, const float* __restrict__ W_sur,
        const float* __restrict__ b_sur, const float* __restrict__ W_gate,
        const float* __restrict__ b_gate, const float* __restrict__ decays,
        const float* __restrict__ halt_w, const float* __restrict__ halt_b,
        float* __restrict__ out, int B)
{
    extern __shared__ float smraw[];
    Smem* S = reinterpret_cast<Smem*>(smraw);
    const int tid = threadIdx.x;
    const int warp = tid >> 5, lane = tid & 31;

    for (int i = tid; i < 2048; i += 256) S->dg[i] = sigm(decays[i]);
    for (int i = tid; i < 2048; i += 256) { int k = i >> 6, m = i & 63; (&S->WbT[0][0])[i]   = W_bridge[m * 32 + k]; }
    for (int i = tid; i < 4096; i += 256) { int m = i >> 6, o = i & 63; (&S->WshT[0][0])[i]  = W_sh[o * 64 + m]; }
    for (int i = tid; i < 2048; i += 256) { int m = i >> 5, s = i & 31; (&S->haltT[0][0])[i] = halt_w[s * 64 + m]; }
    (&S->WbitT[0][0])[tid] = W_bit[(tid & 31) * 8 + (tid >> 5)];
    if (tid < 64) { S->Weng[tid] = W_eng[tid]; S->Wimp[tid] = W_imp[tid]; S->bsh[tid] = b_sh[tid]; }
    if (tid < 32) { S->Wsur[tid] = W_sur[tid]; S->Wgate[tid] = W_gate[tid]; S->bbit[tid] = b_bit[tid]; }
    if (tid < 8)  S->bread[tid] = b_read[tid];
    if (tid < 4)  S->haltb[tid] = halt_b[tid];
    if (tid == 0) { S->beng = b_eng[0]; S->bimp = b_imp[0]; S->bsur = b_sur[0]; S->bgate = b_gate[0]; }
    __syncthreads();

    // Wr resident in registers
    f4u Wreg[8][4];
    #pragma unroll
    for (int o = 0; o < 8; ++o)
        #pragma unroll
        for (int c = 0; c < 4; ++c) {
            f4u w; w.f = *(const float4*)&W_read[o * 512 + c * 128 + lane * 4];
            w.f.x *= 0.25f; w.f.y *= 0.25f; w.f.z *= 0.25f; w.f.w *= 0.25f;
            Wreg[o][c] = w;
        }

    const int og = (lane >> 2) & 7;
    const float brd = S->bread[og];

    float* bufw = &S->buf[warp][0][0];
    unsigned bufu = (unsigned)__cvta_generic_to_shared(bufw) + lane * 16u;
    float* s1w  = &S->s1s[warp][0][0];
    float* s2w  = &S->s2s[warp][0][0];
    float* gssw = &S->gss[warp][0][0];

    const int e0 = ((int)blockIdx.x * 8 + warp) * 4;
    if (e0 < B) {
        prefetch_elem(bufu,          H, e0,     lane);
        prefetch_elem(bufu + 8192u,  H, e0 + 1, lane);
        mlp4(S, x, e0, lane, s1w, s2w, gssw);

        for (int e = e0; e < B; ) {
            int en = e + STRIDE;
            #pragma unroll
            for (int i = 0; i < 4; ++i) {
                CP_WAIT1();                       // elem e+i's group has landed
                const float* bw = bufw + (i & 1) * 2048;

                // ---- decay-reduce ----
                f4u rs[4];
                #pragma unroll
                for (int c = 0; c < 4; ++c) rs[c].f = make_float4(0.f, 0.f, 0.f, 0.f);
                #pragma unroll
                for (int l = 0; l < 4; ++l) {
                    #pragma unroll
                    for (int c = 0; c < 4; ++c) {
                        f4u t; t.f = *(const float4*)&bw[l * 512 + c * 128 + lane * 4];
                        f4u d; d.f = *(const float4*)&S->dg[l * 512 + c * 128 + lane * 4];
                        rs[c].u[0] = ffma2(t.u[0], d.u[0], rs[c].u[0]);
                        rs[c].u[1] = ffma2(t.u[1], d.u[1], rs[c].u[1]);
                    }
                }

                // ---- refill this slot with the next element that will use it ----
                {
                    int pe = (i < 2) ? (e + i + 2) : (en + i - 2);
                    if (pe >= B) pe = 0;          // harmless clamp
                    prefetch_elem(bufu + (unsigned)(i & 1) * 8192u, H, pe, lane);
                }

                // ---- gate fold from per-warp smem ----
                {
                    float4 s2m = *(const float4*)&s2w[i * 64 + ((4 * lane) & 63)];
                    #pragma unroll
                    for (int c = 0; c < 4; ++c) {
                        float g = gssw[i * 8 + (lane >> 4) + 2 * c];
                        rs[c].f.x = fmaf(g, s2m.x, rs[c].f.x);
                        rs[c].f.y = fmaf(g, s2m.y, rs[c].f.y);
                        rs[c].f.z = fmaf(g, s2m.z, rs[c].f.z);
                        rs[c].f.w = fmaf(g, s2m.w, rs[c].f.w);
                    }
                }

                // ---- readout with register-resident Wr ----
                float v[8];
                #pragma unroll
                for (int o = 0; o < 8; ++o) {
                    unsigned long long a0 = 0ull, a1 = 0ull;
                    #pragma unroll
                    for (int c = 0; c < 4; ++c) {
                        a0 = ffma2(rs[c].u[0], Wreg[o][c].u[0], a0);
                        a1 = ffma2(rs[c].u[1], Wreg[o][c].u[1], a1);
                    }
                    f4u pa; pa.u[0] = a0; pa.u[1] = a1;
                    v[o] = (pa.f.x + pa.f.y) + (pa.f.z + pa.f.w);
                }
                float z = fold_reduce8(v, lane);
                if ((lane & 3) == 0) out[(size_t)(e + i) * 8 + og] = z + brd;
            }

            if (en >= B) break;
            mlp4(S, x, en, lane, s1w, s2w, gssw);   // prefetches for en,en+1 already in flight
            e = en;
        }
    }
    CP_WAIT0();
}

extern "C" void kernel_launch(void* const* d_in, const int* in_sizes, int n_in,
                              void* d_out, int out_size) {
    const float* x        = (const float*)d_in[0];
    const float* H        = (const float*)d_in[1];
    const float* W_bit    = (const float*)d_in[2];
    const float* b_bit    = (const float*)d_in[3];
    const float* W_bridge = (const float*)d_in[4];
    const float* W_read   = (const float*)d_in[5];
    const float* b_read   = (const float*)d_in[6];
    const float* W_sh     = (const float*)d_in[7];
    const float* b_sh     = (const float*)d_in[8];
    const float* W_eng    = (const float*)d_in[9];
    const float* b_eng    = (const float*)d_in[10];
    const float* W_imp    = (const float*)d_in[11];
    const float* b_imp    = (const float*)d_in[12];
    const float* W_sur    = (const float*)d_in[13];
    const float* b_sur    = (const float*)d_in[14];
    const float* W_gate   = (const float*)d_in[15];
    const float* b_gate   = (const float*)d_in[16];
    const float* decays   = (const float*)d_in[17];
    const float* halt_w   = (const float*)d_in[18];
    const float* halt_b   = (const float*)d_in[19];
    const int B = in_sizes[0] / 8;
    float* out = (float*)d_out;

    cudaFuncSetAttribute(org_all, cudaFuncAttributeMaxDynamicSharedMemorySize,
                         (int)sizeof(Smem));
    org_all<<<NBLK, 256, sizeof(Smem)>>>(x, H, W_bit, b_bit, W_bridge, W_read,
                                         b_read, W_sh, b_sh, W_eng, b_eng,
                                         W_imp, b_imp, W_sur, b_sur, W_gate,
                                         b_gate, decays, halt_w, halt_b, out, B);
}

// round 17
// speedup vs baseline: 1.2000x; 1.0805x over previous
#include <cuda_runtime.h>

#define NBLK 148
#define STRIDE (NBLK * 8 * 4)    // 4736 elems per sweep

__device__ __forceinline__ float sigm(float v) { return 1.0f / (1.0f + __expf(-v)); }

__device__ __forceinline__ unsigned long long ffma2(unsigned long long a,
                                                    unsigned long long b,
                                                    unsigned long long c) {
    unsigned long long d;
    asm("fma.rn.f32x2 %0, %1, %2, %3;" : "=l"(d) : "l"(a), "l"(b), "l"(c));
    return d;
}
union f4u { float4 f; float a[4]; unsigned long long u[2]; };

__device__ __forceinline__ void cp16(unsigned s, const void* g) {
    asm volatile("cp.async.cg.shared.global [%0], [%1], 16;" :: "r"(s), "l"(g));
}
#define CP_COMMIT() asm volatile("cp.async.commit_group;" ::: "memory")
#define CP_WAIT1()  asm volatile("cp.async.wait_group 1;" ::: "memory")
#define CP_WAIT0()  asm volatile("cp.async.wait_group 0;" ::: "memory")

// fold-reduce 8 lane-local values; result for o=(lane>>2)&7 in each 4-lane group
__device__ __forceinline__ float fold_reduce8(const float* v, int lane) {
    const unsigned FULL = 0xffffffffu;
    bool h16 = (lane & 16) != 0;
    float w[4];
    #pragma unroll
    for (int i = 0; i < 4; ++i) {
        float send = h16 ? v[i] : v[i + 4];
        float t = __shfl_xor_sync(FULL, send, 16);
        w[i] = (h16 ? v[i + 4] : v[i]) + t;
    }
    bool h8 = (lane & 8) != 0;
    float u[2];
    #pragma unroll
    for (int i = 0; i < 2; ++i) {
        float send = h8 ? w[i] : w[i + 2];
        float t = __shfl_xor_sync(FULL, send, 8);
        u[i] = (h8 ? w[i + 2] : w[i]) + t;
    }
    bool h4 = (lane & 4) != 0;
    {
        float send = h4 ? u[0] : u[1];
        float t = __shfl_xor_sync(FULL, send, 4);
        u[0] = (h4 ? u[1] : u[0]) + t;
    }
    u[0] += __shfl_xor_sync(FULL, u[0], 2);
    u[0] += __shfl_xor_sync(FULL, u[0], 1);
    return u[0];
}

// ---------------- shared layout (~183 KB, 1 CTA/SM) -------------------------------------------
struct Smem {
    float dg[2048];          //  8 KB
    float buf[8][2][2048];   // 128 KB  [warp][slot][elem]
    float WbT[32][64];       //  8 KB
    float WshT[64][64];      // 16 KB
    float haltT[64][32];     //  8 KB
    float s2s[8][4][64];     //  8 KB
    float s1s[8][4][32];     //  4 KB
    float gss[8][4][8];      //  1 KB
    float scr[8][8];         // 256 B  per-warp fold scratch
    float WbitT[8][32];      //  1 KB
    float Weng[64], Wimp[64];
    float Wsur[32], Wgate[32];
    float bbit[32], bsh[64];
    float bread[8];
    float haltb[4];
    float beng, bimp, bsur, bgate;
};

// warp-cooperative MLP for 4 consecutive elements e0..e0+3 -> s2s/gss in smem
__device__ __forceinline__ void mlp4(Smem* S, const float* __restrict__ x, int e0,
                                     int lane, float* s1w, float* s2w, float* gssw,
                                     float* scw) {
    const unsigned FULL = 0xffffffffu;
    const int og = (lane >> 2) & 7;
    // ---- s1 ----
    float xv = x[(size_t)e0 * 8 + lane];
    float s1v[4];
    #pragma unroll
    for (int e = 0; e < 4; ++e) {
        float a = S->bbit[lane];
        #pragma unroll
        for (int j = 0; j < 8; ++j) {
            float xj = __shfl_sync(FULL, xv, e * 8 + j);
            a = fmaf(xj, S->WbitT[j][lane], a);
        }
        s1v[e] = a;
        s1w[e * 32 + lane] = a;
    }
    // ---- surprise via single fold-reduce (v[e]=a_e, v[4+e]=b_e) ----
    float sur[4];
    {
        float v[8];
        #pragma unroll
        for (int e = 0; e < 4; ++e) {
            v[e]     = s1v[e] * S->Wsur[lane];
            v[4 + e] = s1v[e] * S->Wgate[lane];
        }
        float fz = fold_reduce8(v, lane);
        if ((lane & 3) == 0) scw[og] = fz;
        __syncwarp();
        #pragma unroll
        for (int e = 0; e < 4; ++e)
            sur[e] = sigm(scw[e] + S->bsur) * sigm(scw[4 + e] + S->bgate);
    }
    __syncwarp();

    // ---- s2 = tanh(s1 @ Wb^T) ----
    {
        float acc0[4] = {0,0,0,0}, acc1[4] = {0,0,0,0};
        #pragma unroll
        for (int k4 = 0; k4 < 8; ++k4) {
            float4 s14[4];
            #pragma unroll
            for (int e = 0; e < 4; ++e) s14[e] = *(const float4*)&s1w[e * 32 + k4 * 4];
            #pragma unroll
            for (int kk = 0; kk < 4; ++kk) {
                float2 w2 = *(const float2*)&S->WbT[k4 * 4 + kk][2 * lane];
                #pragma unroll
                for (int e = 0; e < 4; ++e) {
                    float sv = (&s14[e].x)[kk];
                    acc0[e] = fmaf(sv, w2.x, acc0[e]);
                    acc1[e] = fmaf(sv, w2.y, acc1[e]);
                }
            }
        }
        #pragma unroll
        for (int e = 0; e < 4; ++e) {
            float2 t2; t2.x = tanhf(acc0[e]); t2.y = tanhf(acc1[e]);
            *(float2*)&s2w[e * 64 + 2 * lane] = t2;
        }
    }
    __syncwarp();

    // ---- merged hg + halt ----
    float engimp[4];
    float ha[4] = {0,0,0,0};
    {
        float h0[4] = {0,0,0,0}, h1[4] = {0,0,0,0};
        #pragma unroll
        for (int m4 = 0; m4 < 16; ++m4) {
            float4 s24[4];
            #pragma unroll
            for (int e = 0; e < 4; ++e) s24[e] = *(const float4*)&s2w[e * 64 + m4 * 4];
            #pragma unroll
            for (int mm = 0; mm < 4; ++mm) {
                float2 w2 = *(const float2*)&S->WshT[m4 * 4 + mm][2 * lane];
                float hw  = S->haltT[m4 * 4 + mm][lane];
                #pragma unroll
                for (int e = 0; e < 4; ++e) {
                    float sv = (&s24[e].x)[mm];
                    h0[e] = fmaf(sv, w2.x, h0[e]);
                    h1[e] = fmaf(sv, w2.y, h1[e]);
                    ha[e] = fmaf(sv, hw,   ha[e]);
                }
            }
        }
        // ---- eng/imp via single fold-reduce (v[e]=pe_e, v[4+e]=pi_e) ----
        float we0 = S->Weng[2 * lane], we1 = S->Weng[2 * lane + 1];
        float wi0 = S->Wimp[2 * lane], wi1 = S->Wimp[2 * lane + 1];
        float bs0 = S->bsh[2 * lane],  bs1 = S->bsh[2 * lane + 1];
        float v[8];
        #pragma unroll
        for (int e = 0; e < 4; ++e) {
            float g0 = fmaxf(h0[e] + bs0, 0.f);
            float g1 = fmaxf(h1[e] + bs1, 0.f);
            v[e]     = g0 * we0 + g1 * we1;
            v[4 + e] = g0 * wi0 + g1 * wi1;
        }
        float fz = fold_reduce8(v, lane);
        __syncwarp();                       // protect scr from previous read
        if ((lane & 3) == 0) scw[og] = fz;
        __syncwarp();
        #pragma unroll
        for (int e = 0; e < 4; ++e)
            engimp[e] = sigm(scw[e] + S->beng) * sigm(scw[4 + e] + S->bimp);
    }

    // ---- halt sigmoid -> gss (smem) ----
    float hb = S->haltb[lane >> 3];
    #pragma unroll
    for (int e = 0; e < 4; ++e) {
        float hv = sigm(ha[e] + hb);
        hv += __shfl_xor_sync(FULL, hv, 8);
        hv += __shfl_xor_sync(FULL, hv, 16);
        float g = engimp[e] * sur[e] * hv;
        if (lane < 8) gssw[e * 8 + lane] = g;
    }
    __syncwarp();
}

__device__ __forceinline__ void prefetch_elem(unsigned dst, const float* __restrict__ H,
                                              int e, int lane) {
    const float* src = H + (size_t)e * 2048 + lane * 4;
    #pragma unroll
    for (int i = 0; i < 16; ++i) cp16(dst + i * 512u, src + i * 128);
    CP_COMMIT();
}

__global__ void __launch_bounds__(256, 1)
org_all(const float* __restrict__ x, const float* __restrict__ H,
        const float* __restrict__ W_bit, const float* __restrict__ b_bit,
        const float* __restrict__ W_bridge, const float* __restrict__ W_read,
        const float* __restrict__ b_read, const float* __restrict__ W_sh,
        const float* __restrict__ b_sh, const float* __restrict__ W_eng,
        const float* __restrict__ b_eng, const float* __restrict__ W_imp,
        const float* __restrict__ b_imp, const float* __restrict__ W_sur,
        const float* __restrict__ b_sur, const float* __restrict__ W_gate,
        const float* __restrict__ b_gate, const float* __restrict__ decays,
        const float* __restrict__ halt_w, const float* __restrict__ halt_b,
        float* __restrict__ out, int B)
{
    extern __shared__ float smraw[];
    Smem* S = reinterpret_cast<Smem*>(smraw);
    const int tid = threadIdx.x;
    const int warp = tid >> 5, lane = tid & 31;

    for (int i = tid; i < 2048; i += 256) S->dg[i] = sigm(decays[i]);
    for (int i = tid; i < 2048; i += 256) { int k = i >> 6, m = i & 63; (&S->WbT[0][0])[i]   = W_bridge[m * 32 + k]; }
    for (int i = tid; i < 4096; i += 256) { int m = i >> 6, o = i & 63; (&S->WshT[0][0])[i]  = W_sh[o * 64 + m]; }
    for (int i = tid; i < 2048; i += 256) { int m = i >> 5, s = i & 31; (&S->haltT[0][0])[i] = halt_w[s * 64 + m]; }
    (&S->WbitT[0][0])[tid] = W_bit[(tid & 31) * 8 + (tid >> 5)];
    if (tid < 64) { S->Weng[tid] = W_eng[tid]; S->Wimp[tid] = W_imp[tid]; S->bsh[tid] = b_sh[tid]; }
    if (tid < 32) { S->Wsur[tid] = W_sur[tid]; S->Wgate[tid] = W_gate[tid]; S->bbit[tid] = b_bit[tid]; }
    if (tid < 8)  S->bread[tid] = b_read[tid];
    if (tid < 4)  S->haltb[tid] = halt_b[tid];
    if (tid == 0) { S->beng = b_eng[0]; S->bimp = b_imp[0]; S->bsur = b_sur[0]; S->bgate = b_gate[0]; }
    __syncthreads();

    // Wr resident in registers
    f4u Wreg[8][4];
    #pragma unroll
    for (int o = 0; o < 8; ++o)
        #pragma unroll
        for (int c = 0; c < 4; ++c) {
            f4u w; w.f = *(const float4*)&W_read[o * 512 + c * 128 + lane * 4];
            w.f.x *= 0.25f; w.f.y *= 0.25f; w.f.z *= 0.25f; w.f.w *= 0.25f;
            Wreg[o][c] = w;
        }

    const int og = (lane >> 2) & 7;
    const float brd = S->bread[og];

    float* bufw = &S->buf[warp][0][0];
    unsigned bufu = (unsigned)__cvta_generic_to_shared(bufw) + lane * 16u;
    float* s1w  = &S->s1s[warp][0][0];
    float* s2w  = &S->s2s[warp][0][0];
    float* gssw = &S->gss[warp][0][0];
    float* scw  = &S->scr[warp][0];

    const int e0 = ((int)blockIdx.x * 8 + warp) * 4;
    if (e0 < B) {
        prefetch_elem(bufu,          H, e0,     lane);
        prefetch_elem(bufu + 8192u,  H, e0 + 1, lane);
        mlp4(S, x, e0, lane, s1w, s2w, gssw, scw);

        for (int e = e0; e < B; ) {
            int en = e + STRIDE;
            #pragma unroll
            for (int i = 0; i < 4; ++i) {
                CP_WAIT1();                       // elem e+i's group has landed
                const float* bw = bufw + (i & 1) * 2048;

                // ---- decay-reduce ----
                f4u rs[4];
                #pragma unroll
                for (int c = 0; c < 4; ++c) rs[c].f = make_float4(0.f, 0.f, 0.f, 0.f);
                #pragma unroll
                for (int l = 0; l < 4; ++l) {
                    #pragma unroll
                    for (int c = 0; c < 4; ++c) {
                        f4u t; t.f = *(const float4*)&bw[l * 512 + c * 128 + lane * 4];
                        f4u d; d.f = *(const float4*)&S->dg[l * 512 + c * 128 + lane * 4];
                        rs[c].u[0] = ffma2(t.u[0], d.u[0], rs[c].u[0]);
                        rs[c].u[1] = ffma2(t.u[1], d.u[1], rs[c].u[1]);
                    }
                }

                // ---- refill this slot with the next element that will use it ----
                {
                    int pe = (i < 2) ? (e + i + 2) : (en + i - 2);
                    if (pe >= B) pe = 0;          // harmless clamp
                    prefetch_elem(bufu + (unsigned)(i & 1) * 8192u, H, pe, lane);
                }

                // ---- gate fold from per-warp smem ----
                {
                    float4 s2m = *(const float4*)&s2w[i * 64 + ((4 * lane) & 63)];
                    #pragma unroll
                    for (int c = 0; c < 4; ++c) {
                        float g = gssw[i * 8 + (lane >> 4) + 2 * c];
                        rs[c].f.x = fmaf(g, s2m.x, rs[c].f.x);
                        rs[c].f.y = fmaf(g, s2m.y, rs[c].f.y);
                        rs[c].f.z = fmaf(g, s2m.z, rs[c].f.z);
                        rs[c].f.w = fmaf(g, s2m.w, rs[c].f.w);
                    }
                }

                // ---- readout with register-resident Wr ----
                float v[8];
                #pragma unroll
                for (int o = 0; o < 8; ++o) {
                    unsigned long long a0 = 0ull, a1 = 0ull;
                    #pragma unroll
                    for (int c = 0; c < 4; ++c) {
                        a0 = ffma2(rs[c].u[0], Wreg[o][c].u[0], a0);
                        a1 = ffma2(rs[c].u[1], Wreg[o][c].u[1], a1);
                    }
                    f4u pa; pa.u[0] = a0; pa.u[1] = a1;
                    v[o] = (pa.f.x + pa.f.y) + (pa.f.z + pa.f.w);
                }
                float z = fold_reduce8(v, lane);
                if ((lane & 3) == 0) out[(size_t)(e + i) * 8 + og] = z + brd;
            }

            if (en >= B) break;
            mlp4(S, x, en, lane, s1w, s2w, gssw, scw);   // prefetches for en,en+1 in flight
            e = en;
        }
    }
    CP_WAIT0();
}

extern "C" void kernel_launch(void* const* d_in, const int* in_sizes, int n_in,
                              void* d_out, int out_size) {
    const float* x        = (const float*)d_in[0];
    const float* H        = (const float*)d_in[1];
    const float* W_bit    = (const float*)d_in[2];
    const float* b_bit    = (const float*)d_in[3];
    const float* W_bridge = (const float*)d_in[4];
    const float* W_read   = (const float*)d_in[5];
    const float* b_read   = (const float*)d_in[6];
    const float* W_sh     = (const float*)d_in[7];
    const float* b_sh     = (const float*)d_in[8];
    const float* W_eng    = (const float*)d_in[9];
    const float* b_eng    = (const float*)d_in[10];
    const float* W_imp    = (const float*)d_in[11];
    const float* b_imp    = (const float*)d_in[12];
    const float* W_sur    = (const float*)d_in[13];
    const float* b_sur    = (const float*)d_in[14];
    const float* W_gate   = (const float*)d_in[15];
    const float* b_gate   = (const float*)d_in[16];
    const float* decays   = (const float*)d_in[17];
    const float* halt_w   = (const float*)d_in[18];
    const float* halt_b   = (const float*)d_in[19];
    const int B = in_sizes[0] / 8;
    float* out = (float*)d_out;

    cudaFuncSetAttribute(org_all, cudaFuncAttributeMaxDynamicSharedMemorySize,
                         (int)sizeof(Smem));
    org_all<<<NBLK, 256, sizeof(Smem)>>>(x, H, W_bit, b_bit, W_bridge, W_read,
                                         b_read, W_sh, b_sh, W_eng, b_eng,
                                         W_imp, b_imp, W_sur, b_sur, W_gate,
                                         b_gate, decays, halt_w, halt_b, out, B);
}